// round 5
// baseline (speedup 1.0000x reference)
#include <cuda_runtime.h>

// Swin window attention, fused per-window kernel, v4:
// v3 + software-pipelined weight prefetch (P1/P5) + rel_table & mask staged in smem.
// B=32, nW=64 -> 2048 windows; N=49 tokens, C=128, H=4 heads, hd=32.

#define NWIN 64
#define NTOK 49
#define CDIM 128
#define NHEAD 4
#define HDIM 32
#define TPB 512
#define QPITCH 130

using u64 = unsigned long long;

__device__ __forceinline__ void fma2(u64& d, u64 a, u64 b) {
    asm("fma.rn.f32x2 %0, %1, %2, %0;" : "+l"(d) : "l"(a), "l"(b));
}
__device__ __forceinline__ u64 pack2(float lo, float hi) {
    u64 r; asm("mov.b64 %0, {%1, %2};" : "=l"(r) : "f"(lo), "f"(hi)); return r;
}
__device__ __forceinline__ float2 unpack2(u64 v) {
    float2 r; asm("mov.b64 {%0, %1}, %2;" : "=f"(r.x), "=f"(r.y) : "l"(v)); return r;
}

// shared memory layout (floats)
static constexpr int OFF_XT   = 0;                       // [128][52]; later s_o [49][128]
static constexpr int OFF_Q    = OFF_XT + 128 * 52;       // 6656, [49][130]
static constexpr int OFF_KT   = 13028;                   // [128][52] (16B aligned)
static constexpr int OFF_V    = OFF_KT + 128 * 52;       // 19684, [49][128]
static constexpr int OFF_ATTN = OFF_V + NTOK * CDIM;     // 25956, [196][52]
static constexpr int OFF_REL  = OFF_ATTN + (NHEAD * NTOK) * 52;  // 36148, 169*4
static constexpr int OFF_MASK = OFF_REL + 169 * NHEAD;   // 36824, 49*49
static constexpr int SMEM_FLOATS = OFF_MASK + NTOK * NTOK + 3;   // 39228
static constexpr int SMEM_BYTES  = SMEM_FLOATS * 4;      // 156912

__global__ __launch_bounds__(TPB, 1)
void swin_window_attn_kernel(const float* __restrict__ x_all,
                             const float* __restrict__ mask,
                             const float* __restrict__ qkv_w,
                             const float* __restrict__ qkv_b,
                             const float* __restrict__ proj_w,
                             const float* __restrict__ proj_b,
                             const float* __restrict__ rel_table,
                             float* __restrict__ out)
{
    extern __shared__ float sm[];
    float* s_xT   = sm + OFF_XT;     // [128][52]
    float* s_q    = sm + OFF_Q;      // [49][130]
    float* s_kT   = sm + OFF_KT;     // [128][52]
    float* s_v    = sm + OFF_V;      // [49][128]
    float* s_attn = sm + OFF_ATTN;   // [196][52]
    float* s_rel  = sm + OFF_REL;    // [169][4]
    float* s_mask = sm + OFF_MASK;   // [49][49]
    float* s_o    = sm + OFF_XT;     // alias: x dead after phase 1

    const int tid = threadIdx.x;
    const int blk = blockIdx.x;
    const float* x  = x_all + (size_t)blk * (NTOK * CDIM);
    const float* mw = mask  + (size_t)(blk & (NWIN - 1)) * (NTOK * NTOK);

    // ---- stage x (transposed), rel_table, mask into smem ----
    for (int idx = tid; idx < NTOK * CDIM; idx += TPB) {
        const int r = idx >> 7;
        const int k = idx & 127;
        s_xT[k * 52 + r] = x[idx];
    }
    for (int idx = tid; idx < 169 * NHEAD; idx += TPB) s_rel[idx] = __ldg(&rel_table[idx]);
    for (int idx = tid; idx < NTOK * NTOK; idx += TPB) s_mask[idx] = __ldg(&mw[idx]);
    __syncthreads();

    const int col   = tid & 127;
    const int g     = tid >> 7;       // 0..3
    const int rbase = g * 12;         // 0,12,24,36
    const int rcnt  = (g == 3) ? 13 : 12;

    // ---- phase 1: QKV GEMM, f32x2, 2-stage weight prefetch (2 k-steps/stage) ----
    {
        u64 a0[6], a1[6], a2[6];
        float s0 = 0.f, s1 = 0.f, s2 = 0.f;
        #pragma unroll
        for (int p = 0; p < 6; ++p) { a0[p] = 0ull; a1[p] = 0ull; a2[p] = 0ull; }

        float wbuf[2][2][3];   // [stage][k-in-stage][chunk]
        {
            const float* r0 = qkv_w;
            const float* r1 = qkv_w + 384;
            wbuf[0][0][0] = __ldg(&r0[col]);       wbuf[0][0][1] = __ldg(&r0[128 + col]);
            wbuf[0][0][2] = __ldg(&r0[256 + col]);
            wbuf[0][1][0] = __ldg(&r1[col]);       wbuf[0][1][1] = __ldg(&r1[128 + col]);
            wbuf[0][1][2] = __ldg(&r1[256 + col]);
        }

        #pragma unroll 1
        for (int k2 = 0; k2 < 64; ++k2) {
            const int cur = k2 & 1;
            const int nxt = cur ^ 1;
            if (k2 < 63) {
                const float* r0 = qkv_w + (size_t)(k2 + 1) * 2 * 384;
                const float* r1 = r0 + 384;
                wbuf[nxt][0][0] = __ldg(&r0[col]);       wbuf[nxt][0][1] = __ldg(&r0[128 + col]);
                wbuf[nxt][0][2] = __ldg(&r0[256 + col]);
                wbuf[nxt][1][0] = __ldg(&r1[col]);       wbuf[nxt][1][1] = __ldg(&r1[128 + col]);
                wbuf[nxt][1][2] = __ldg(&r1[256 + col]);
            }
            #pragma unroll
            for (int t = 0; t < 2; ++t) {
                const int kk = k2 * 2 + t;
                const float w0 = wbuf[cur][t][0];
                const float w1 = wbuf[cur][t][1];
                const float w2 = wbuf[cur][t][2];
                const u64 w0p = pack2(w0, w0);
                const u64 w1p = pack2(w1, w1);
                const u64 w2p = pack2(w2, w2);

                const ulonglong2* xr = reinterpret_cast<const ulonglong2*>(&s_xT[kk * 52 + rbase]);
                const ulonglong2 p01 = xr[0];
                const ulonglong2 p23 = xr[1];
                const ulonglong2 p45 = xr[2];
                const float x12 = s_xT[kk * 52 + rbase + 12];

                fma2(a0[0], p01.x, w0p); fma2(a0[1], p01.y, w0p);
                fma2(a0[2], p23.x, w0p); fma2(a0[3], p23.y, w0p);
                fma2(a0[4], p45.x, w0p); fma2(a0[5], p45.y, w0p);
                fma2(a1[0], p01.x, w1p); fma2(a1[1], p01.y, w1p);
                fma2(a1[2], p23.x, w1p); fma2(a1[3], p23.y, w1p);
                fma2(a1[4], p45.x, w1p); fma2(a1[5], p45.y, w1p);
                fma2(a2[0], p01.x, w2p); fma2(a2[1], p01.y, w2p);
                fma2(a2[2], p23.x, w2p); fma2(a2[3], p23.y, w2p);
                fma2(a2[4], p45.x, w2p); fma2(a2[5], p45.y, w2p);
                s0 += x12 * w0;  s1 += x12 * w1;  s2 += x12 * w2;
            }
        }

        const float b0 = __ldg(&qkv_b[col]);
        const float b1 = __ldg(&qkv_b[128 + col]);
        const float b2 = __ldg(&qkv_b[256 + col]);
        #pragma unroll
        for (int p = 0; p < 6; ++p) {
            const int r = rbase + 2 * p;
            const float2 f0 = unpack2(a0[p]);
            const float2 f1 = unpack2(a1[p]);
            const float2 f2 = unpack2(a2[p]);
            s_q[r * QPITCH + col]       = f0.x + b0;
            s_q[(r + 1) * QPITCH + col] = f0.y + b0;
            s_kT[col * 52 + r]          = f1.x + b1;
            s_kT[col * 52 + r + 1]      = f1.y + b1;
            s_v[r * 128 + col]          = f2.x + b2;
            s_v[(r + 1) * 128 + col]    = f2.y + b2;
        }
        if (rcnt == 13) {
            const int r = rbase + 12;
            s_q[r * QPITCH + col] = s0 + b0;
            s_kT[col * 52 + r]    = s1 + b1;
            s_v[r * 128 + col]    = s2 + b2;
        }
    }
    __syncthreads();

    // ---- phase 2: scores + bias + mask; thread = (h, row-pair, 4 adjacent j) ----
    {
        const float scale = 0.17677669529663687f;   // 1/sqrt(32)
        for (int u = tid; u < NHEAD * 25 * 13; u += TPB) {
            const int h   = u / (25 * 13);
            const int rem = u - h * (25 * 13);
            const int ib  = rem / 13;
            const int jg  = rem - ib * 13;
            const int j4  = jg * 4;
            const int i0  = ib;
            const bool has1 = (ib < 24);
            const int i1  = has1 ? ib + 25 : ib;

            const float* q0 = &s_q[i0 * QPITCH + h * HDIM];
            const float* q1 = &s_q[i1 * QPITCH + h * HDIM];
            const float* kc = &s_kT[(h * HDIM) * 52 + j4];

            u64 acc0a = 0ull, acc0b = 0ull, acc1a = 0ull, acc1b = 0ull;
            #pragma unroll
            for (int d = 0; d < HDIM; ++d) {
                const ulonglong2 kv = *reinterpret_cast<const ulonglong2*>(&kc[d * 52]);
                const float qv0 = q0[d];
                const float qv1 = q1[d];
                const u64 q0p = pack2(qv0, qv0);
                const u64 q1p = pack2(qv1, qv1);
                fma2(acc0a, kv.x, q0p); fma2(acc0b, kv.y, q0p);
                fma2(acc1a, kv.x, q1p); fma2(acc1b, kv.y, q1p);
            }
            const float2 r0a = unpack2(acc0a), r0b = unpack2(acc0b);
            const float2 r1a = unpack2(acc1a), r1b = unpack2(acc1b);
            float sv0[4] = {r0a.x, r0a.y, r0b.x, r0b.y};
            float sv1[4] = {r1a.x, r1a.y, r1b.x, r1b.y};

            const int yi0 = i0 / 7, xi0 = i0 - yi0 * 7;
            const int yi1 = i1 / 7, xi1 = i1 - yi1 * 7;
            float* arow0 = &s_attn[(h * NTOK + i0) * 52];
            float* arow1 = &s_attn[(h * NTOK + i1) * 52];
            const float* mrow0 = &s_mask[i0 * NTOK];
            const float* mrow1 = &s_mask[i1 * NTOK];
            #pragma unroll
            for (int jj = 0; jj < 4; ++jj) {
                const int j = j4 + jj;
                if (j < NTOK) {
                    const int yj = j / 7, xj = j - yj * 7;
                    const int r0 = (yi0 - yj + 6) * 13 + (xi0 - xj + 6);
                    arow0[j] = sv0[jj] * scale + s_rel[r0 * NHEAD + h] + mrow0[j];
                    if (has1) {
                        const int r1 = (yi1 - yj + 6) * 13 + (xi1 - xj + 6);
                        arow1[j] = sv1[jj] * scale + s_rel[r1 * NHEAD + h] + mrow1[j];
                    }
                }
            }
        }
    }
    __syncthreads();

    // ---- phase 3: softmax, one warp per (head, query-row) ----
    {
        const int warp = tid >> 5;
        const int lane = tid & 31;
        for (int row = warp; row < NHEAD * NTOK; row += TPB / 32) {
            float* a = &s_attn[row * 52];
            float v0 = (lane < NTOK)      ? a[lane]      : -1e30f;
            float v1 = (lane + 32 < NTOK) ? a[lane + 32] : -1e30f;
            float m = fmaxf(v0, v1);
            #pragma unroll
            for (int off = 16; off; off >>= 1)
                m = fmaxf(m, __shfl_xor_sync(0xffffffffu, m, off));
            float e0 = (lane < NTOK)      ? __expf(v0 - m) : 0.f;
            float e1 = (lane + 32 < NTOK) ? __expf(v1 - m) : 0.f;
            float ssum = e0 + e1;
            #pragma unroll
            for (int off = 16; off; off >>= 1)
                ssum += __shfl_xor_sync(0xffffffffu, ssum, off);
            const float inv = 1.0f / ssum;
            if (lane < NTOK)      a[lane]      = e0 * inv;
            if (lane + 32 < NTOK) a[lane + 32] = e1 * inv;
        }
    }
    __syncthreads();

    // ---- phase 4: attn @ v; thread = (row-pair, 4 adjacent c) ----
    for (int u = tid; u < 25 * 32; u += TPB) {
        const int ib = u >> 5;
        const int cg = u & 31;
        const int c4 = cg * 4;
        const int h  = cg >> 3;
        const int i0 = ib;
        const bool has1 = (ib < 24);
        const int i1 = has1 ? ib + 25 : ib;

        const float* a0r = &s_attn[(h * NTOK + i0) * 52];
        const float* a1r = &s_attn[(h * NTOK + i1) * 52];
        const float* vr  = &s_v[c4];

        u64 o0a = 0ull, o0b = 0ull, o1a = 0ull, o1b = 0ull;
        #pragma unroll 7
        for (int j = 0; j < NTOK; ++j) {
            const ulonglong2 vv = *reinterpret_cast<const ulonglong2*>(&vr[j * 128]);
            const float av0 = a0r[j];
            const float av1 = a1r[j];
            const u64 a0p = pack2(av0, av0);
            const u64 a1p = pack2(av1, av1);
            fma2(o0a, vv.x, a0p); fma2(o0b, vv.y, a0p);
            fma2(o1a, vv.x, a1p); fma2(o1b, vv.y, a1p);
        }
        const float2 f0a = unpack2(o0a), f0b = unpack2(o0b);
        float4 w0; w0.x = f0a.x; w0.y = f0a.y; w0.z = f0b.x; w0.w = f0b.y;
        *reinterpret_cast<float4*>(&s_o[i0 * 128 + c4]) = w0;
        if (has1) {
            const float2 f1a = unpack2(o1a), f1b = unpack2(o1b);
            float4 w1; w1.x = f1a.x; w1.y = f1a.y; w1.z = f1b.x; w1.w = f1b.y;
            *reinterpret_cast<float4*>(&s_o[i1 * 128 + c4]) = w1;
        }
    }
    __syncthreads();

    // ---- phase 5: output projection, f32x2 k-paired, 2-stage weight prefetch ----
    {
        u64 acc[13];
        #pragma unroll
        for (int i = 0; i < 13; ++i) acc[i] = 0ull;

        float wc[2][4];
        {
            wc[0][0] = __ldg(&proj_w[0 * 128 + col]);
            wc[0][1] = __ldg(&proj_w[1 * 128 + col]);
            wc[0][2] = __ldg(&proj_w[2 * 128 + col]);
            wc[0][3] = __ldg(&proj_w[3 * 128 + col]);
        }

        #pragma unroll 1
        for (int k4 = 0; k4 < 32; ++k4) {
            const int cur = k4 & 1;
            const int nxt = cur ^ 1;
            if (k4 < 31) {
                const int kn = (k4 + 1) * 4;
                wc[nxt][0] = __ldg(&proj_w[(size_t)(kn + 0) * 128 + col]);
                wc[nxt][1] = __ldg(&proj_w[(size_t)(kn + 1) * 128 + col]);
                wc[nxt][2] = __ldg(&proj_w[(size_t)(kn + 2) * 128 + col]);
                wc[nxt][3] = __ldg(&proj_w[(size_t)(kn + 3) * 128 + col]);
            }
            const int kk = k4 * 4;
            const u64 w01 = pack2(wc[cur][0], wc[cur][1]);
            const u64 w23 = pack2(wc[cur][2], wc[cur][3]);
            #pragma unroll
            for (int i = 0; i < 13; ++i) {
                const ulonglong2 ov = *reinterpret_cast<const ulonglong2*>(&s_o[(rbase + i) * 128 + kk]);
                fma2(acc[i], ov.x, w01);
                fma2(acc[i], ov.y, w23);
            }
        }
        const float bv = __ldg(&proj_b[col]);
        float* o = out + (size_t)blk * (NTOK * CDIM);
        for (int i = 0; i < rcnt; ++i) {
            const float2 f = unpack2(acc[i]);
            o[(rbase + i) * 128 + col] = f.x + f.y + bv;
        }
    }
}

extern "C" void kernel_launch(void* const* d_in, const int* in_sizes, int n_in,
                              void* d_out, int out_size)
{
    const float* x      = (const float*)d_in[0];
    const float* mask   = (const float*)d_in[1];
    const float* qkv_w  = (const float*)d_in[2];
    const float* qkv_b  = (const float*)d_in[3];
    const float* proj_w = (const float*)d_in[4];
    const float* proj_b = (const float*)d_in[5];
    const float* rel    = (const float*)d_in[6];
    float* out = (float*)d_out;

    cudaFuncSetAttribute(swin_window_attn_kernel,
                         cudaFuncAttributeMaxDynamicSharedMemorySize, SMEM_BYTES);
    swin_window_attn_kernel<<<2048, TPB, SMEM_BYTES>>>(
        x, mask, qkv_w, qkv_b, proj_w, proj_b, rel, out);
}

// round 7
// speedup vs baseline: 1.3147x; 1.3147x over previous
#include <cuda_runtime.h>

// Swin window attention, fused per-window kernel, v5 (re-bench after infra failure):
// v3 + statically-indexed (register) double-buffered weight prefetch + rel/mask in smem.
// B=32, nW=64 -> 2048 windows; N=49 tokens, C=128, H=4 heads, hd=32.

#define NWIN 64
#define NTOK 49
#define CDIM 128
#define NHEAD 4
#define HDIM 32
#define TPB 512
#define QPITCH 130

using u64 = unsigned long long;

__device__ __forceinline__ void fma2(u64& d, u64 a, u64 b) {
    asm("fma.rn.f32x2 %0, %1, %2, %0;" : "+l"(d) : "l"(a), "l"(b));
}
__device__ __forceinline__ u64 pack2(float lo, float hi) {
    u64 r; asm("mov.b64 %0, {%1, %2};" : "=l"(r) : "f"(lo), "f"(hi)); return r;
}
__device__ __forceinline__ float2 unpack2(u64 v) {
    float2 r; asm("mov.b64 {%0, %1}, %2;" : "=f"(r.x), "=f"(r.y) : "l"(v)); return r;
}

// shared memory layout (floats)
static constexpr int OFF_XT   = 0;                       // [128][52]; later s_o [49][128]
static constexpr int OFF_Q    = OFF_XT + 128 * 52;       // 6656, [49][130]
static constexpr int OFF_KT   = 13028;                   // [128][52] (16B aligned)
static constexpr int OFF_V    = OFF_KT + 128 * 52;       // 19684, [49][128]
static constexpr int OFF_ATTN = OFF_V + NTOK * CDIM;     // 25956, [196][52]
static constexpr int OFF_REL  = OFF_ATTN + (NHEAD * NTOK) * 52;  // 36148, 169*4
static constexpr int OFF_MASK = OFF_REL + 169 * NHEAD;   // 36824, 49*49
static constexpr int SMEM_FLOATS = OFF_MASK + NTOK * NTOK + 3;   // 39228
static constexpr int SMEM_BYTES  = SMEM_FLOATS * 4;      // 156912

__global__ __launch_bounds__(TPB, 1)
void swin_window_attn_kernel(const float* __restrict__ x_all,
                             const float* __restrict__ mask,
                             const float* __restrict__ qkv_w,
                             const float* __restrict__ qkv_b,
                             const float* __restrict__ proj_w,
                             const float* __restrict__ proj_b,
                             const float* __restrict__ rel_table,
                             float* __restrict__ out)
{
    extern __shared__ float sm[];
    float* s_xT   = sm + OFF_XT;     // [128][52]
    float* s_q    = sm + OFF_Q;      // [49][130]
    float* s_kT   = sm + OFF_KT;     // [128][52]
    float* s_v    = sm + OFF_V;      // [49][128]
    float* s_attn = sm + OFF_ATTN;   // [196][52]
    float* s_rel  = sm + OFF_REL;    // [169][4]
    float* s_mask = sm + OFF_MASK;   // [49][49]
    float* s_o    = sm + OFF_XT;     // alias: x dead after phase 1

    const int tid = threadIdx.x;
    const int blk = blockIdx.x;
    const float* x  = x_all + (size_t)blk * (NTOK * CDIM);
    const float* mw = mask  + (size_t)(blk & (NWIN - 1)) * (NTOK * NTOK);

    // ---- stage x (transposed), rel_table, mask into smem ----
    for (int idx = tid; idx < NTOK * CDIM; idx += TPB) {
        const int r = idx >> 7;
        const int k = idx & 127;
        s_xT[k * 52 + r] = x[idx];
    }
    for (int idx = tid; idx < 169 * NHEAD; idx += TPB) s_rel[idx] = __ldg(&rel_table[idx]);
    for (int idx = tid; idx < NTOK * NTOK; idx += TPB) s_mask[idx] = __ldg(&mw[idx]);
    __syncthreads();

    const int col   = tid & 127;
    const int g     = tid >> 7;       // 0..3
    const int rbase = g * 12;         // 0,12,24,36
    const int rcnt  = (g == 3) ? 13 : 12;

    // ---- phase 1: QKV GEMM, f32x2, register double-buffered weight prefetch ----
    {
        u64 a0[6], a1[6], a2[6];
        float s0 = 0.f, s1 = 0.f, s2 = 0.f;
        #pragma unroll
        for (int p = 0; p < 6; ++p) { a0[p] = 0ull; a1[p] = 0ull; a2[p] = 0ull; }

        const float* wq = qkv_w + col;   // row stride 384

        // named double buffers: each stage = 2 k-steps x 3 chunks
        float A00, A01, A02, A10, A11, A12;
        float B00, B01, B02, B10, B11, B12;

        // preload stage A (k = 0,1)
        A00 = __ldg(&wq[0]);       A01 = __ldg(&wq[128]);       A02 = __ldg(&wq[256]);
        A10 = __ldg(&wq[384]);     A11 = __ldg(&wq[384 + 128]); A12 = __ldg(&wq[384 + 256]);

        #pragma unroll 1
        for (int k4 = 0; k4 < 128; k4 += 4) {
            // prefetch stage B (k = k4+2, k4+3); last iter has them in range (126,127)
            {
                const float* r0 = wq + (size_t)(k4 + 2) * 384;
                const float* r1 = r0 + 384;
                B00 = __ldg(&r0[0]); B01 = __ldg(&r0[128]); B02 = __ldg(&r0[256]);
                B10 = __ldg(&r1[0]); B11 = __ldg(&r1[128]); B12 = __ldg(&r1[256]);
            }
            // compute stage A (k = k4, k4+1)
            #pragma unroll
            for (int t = 0; t < 2; ++t) {
                const int kk = k4 + t;
                const float w0 = t ? A10 : A00;
                const float w1 = t ? A11 : A01;
                const float w2 = t ? A12 : A02;
                const u64 w0p = pack2(w0, w0);
                const u64 w1p = pack2(w1, w1);
                const u64 w2p = pack2(w2, w2);
                const ulonglong2* xr = reinterpret_cast<const ulonglong2*>(&s_xT[kk * 52 + rbase]);
                const ulonglong2 p01 = xr[0];
                const ulonglong2 p23 = xr[1];
                const ulonglong2 p45 = xr[2];
                const float x12 = s_xT[kk * 52 + rbase + 12];
                fma2(a0[0], p01.x, w0p); fma2(a0[1], p01.y, w0p);
                fma2(a0[2], p23.x, w0p); fma2(a0[3], p23.y, w0p);
                fma2(a0[4], p45.x, w0p); fma2(a0[5], p45.y, w0p);
                fma2(a1[0], p01.x, w1p); fma2(a1[1], p01.y, w1p);
                fma2(a1[2], p23.x, w1p); fma2(a1[3], p23.y, w1p);
                fma2(a1[4], p45.x, w1p); fma2(a1[5], p45.y, w1p);
                fma2(a2[0], p01.x, w2p); fma2(a2[1], p01.y, w2p);
                fma2(a2[2], p23.x, w2p); fma2(a2[3], p23.y, w2p);
                fma2(a2[4], p45.x, w2p); fma2(a2[5], p45.y, w2p);
                s0 += x12 * w0;  s1 += x12 * w1;  s2 += x12 * w2;
            }
            // prefetch stage A (k = k4+4, k4+5), clamped on final iteration
            {
                const int kn = (k4 + 4 < 128) ? (k4 + 4) : 126;
                const float* r0 = wq + (size_t)kn * 384;
                const float* r1 = r0 + 384;
                A00 = __ldg(&r0[0]); A01 = __ldg(&r0[128]); A02 = __ldg(&r0[256]);
                A10 = __ldg(&r1[0]); A11 = __ldg(&r1[128]); A12 = __ldg(&r1[256]);
            }
            // compute stage B (k = k4+2, k4+3)
            #pragma unroll
            for (int t = 0; t < 2; ++t) {
                const int kk = k4 + 2 + t;
                const float w0 = t ? B10 : B00;
                const float w1 = t ? B11 : B01;
                const float w2 = t ? B12 : B02;
                const u64 w0p = pack2(w0, w0);
                const u64 w1p = pack2(w1, w1);
                const u64 w2p = pack2(w2, w2);
                const ulonglong2* xr = reinterpret_cast<const ulonglong2*>(&s_xT[kk * 52 + rbase]);
                const ulonglong2 p01 = xr[0];
                const ulonglong2 p23 = xr[1];
                const ulonglong2 p45 = xr[2];
                const float x12 = s_xT[kk * 52 + rbase + 12];
                fma2(a0[0], p01.x, w0p); fma2(a0[1], p01.y, w0p);
                fma2(a0[2], p23.x, w0p); fma2(a0[3], p23.y, w0p);
                fma2(a0[4], p45.x, w0p); fma2(a0[5], p45.y, w0p);
                fma2(a1[0], p01.x, w1p); fma2(a1[1], p01.y, w1p);
                fma2(a1[2], p23.x, w1p); fma2(a1[3], p23.y, w1p);
                fma2(a1[4], p45.x, w1p); fma2(a1[5], p45.y, w1p);
                fma2(a2[0], p01.x, w2p); fma2(a2[1], p01.y, w2p);
                fma2(a2[2], p23.x, w2p); fma2(a2[3], p23.y, w2p);
                fma2(a2[4], p45.x, w2p); fma2(a2[5], p45.y, w2p);
                s0 += x12 * w0;  s1 += x12 * w1;  s2 += x12 * w2;
            }
        }

        const float b0 = __ldg(&qkv_b[col]);
        const float b1 = __ldg(&qkv_b[128 + col]);
        const float b2 = __ldg(&qkv_b[256 + col]);
        #pragma unroll
        for (int p = 0; p < 6; ++p) {
            const int r = rbase + 2 * p;
            const float2 f0 = unpack2(a0[p]);
            const float2 f1 = unpack2(a1[p]);
            const float2 f2 = unpack2(a2[p]);
            s_q[r * QPITCH + col]       = f0.x + b0;
            s_q[(r + 1) * QPITCH + col] = f0.y + b0;
            s_kT[col * 52 + r]          = f1.x + b1;
            s_kT[col * 52 + r + 1]      = f1.y + b1;
            s_v[r * 128 + col]          = f2.x + b2;
            s_v[(r + 1) * 128 + col]    = f2.y + b2;
        }
        if (rcnt == 13) {
            const int r = rbase + 12;
            s_q[r * QPITCH + col] = s0 + b0;
            s_kT[col * 52 + r]    = s1 + b1;
            s_v[r * 128 + col]    = s2 + b2;
        }
    }
    __syncthreads();

    // ---- phase 2: scores + bias + mask; thread = (h, row-pair, 4 adjacent j) ----
    {
        const float scale = 0.17677669529663687f;   // 1/sqrt(32)
        for (int u = tid; u < NHEAD * 25 * 13; u += TPB) {
            const int h   = u / (25 * 13);
            const int rem = u - h * (25 * 13);
            const int ib  = rem / 13;
            const int jg  = rem - ib * 13;
            const int j4  = jg * 4;
            const int i0  = ib;
            const bool has1 = (ib < 24);
            const int i1  = has1 ? ib + 25 : ib;

            const float* q0 = &s_q[i0 * QPITCH + h * HDIM];
            const float* q1 = &s_q[i1 * QPITCH + h * HDIM];
            const float* kc = &s_kT[(h * HDIM) * 52 + j4];

            u64 acc0a = 0ull, acc0b = 0ull, acc1a = 0ull, acc1b = 0ull;
            #pragma unroll
            for (int d = 0; d < HDIM; ++d) {
                const ulonglong2 kv = *reinterpret_cast<const ulonglong2*>(&kc[d * 52]);
                const float qv0 = q0[d];
                const float qv1 = q1[d];
                const u64 q0p = pack2(qv0, qv0);
                const u64 q1p = pack2(qv1, qv1);
                fma2(acc0a, kv.x, q0p); fma2(acc0b, kv.y, q0p);
                fma2(acc1a, kv.x, q1p); fma2(acc1b, kv.y, q1p);
            }
            const float2 r0a = unpack2(acc0a), r0b = unpack2(acc0b);
            const float2 r1a = unpack2(acc1a), r1b = unpack2(acc1b);
            float sv0[4] = {r0a.x, r0a.y, r0b.x, r0b.y};
            float sv1[4] = {r1a.x, r1a.y, r1b.x, r1b.y};

            const int yi0 = i0 / 7, xi0 = i0 - yi0 * 7;
            const int yi1 = i1 / 7, xi1 = i1 - yi1 * 7;
            float* arow0 = &s_attn[(h * NTOK + i0) * 52];
            float* arow1 = &s_attn[(h * NTOK + i1) * 52];
            const float* mrow0 = &s_mask[i0 * NTOK];
            const float* mrow1 = &s_mask[i1 * NTOK];
            #pragma unroll
            for (int jj = 0; jj < 4; ++jj) {
                const int j = j4 + jj;
                if (j < NTOK) {
                    const int yj = j / 7, xj = j - yj * 7;
                    const int r0 = (yi0 - yj + 6) * 13 + (xi0 - xj + 6);
                    arow0[j] = sv0[jj] * scale + s_rel[r0 * NHEAD + h] + mrow0[j];
                    if (has1) {
                        const int r1 = (yi1 - yj + 6) * 13 + (xi1 - xj + 6);
                        arow1[j] = sv1[jj] * scale + s_rel[r1 * NHEAD + h] + mrow1[j];
                    }
                }
            }
        }
    }
    __syncthreads();

    // ---- phase 3: softmax, one warp per (head, query-row) ----
    {
        const int warp = tid >> 5;
        const int lane = tid & 31;
        for (int row = warp; row < NHEAD * NTOK; row += TPB / 32) {
            float* a = &s_attn[row * 52];
            float v0 = (lane < NTOK)      ? a[lane]      : -1e30f;
            float v1 = (lane + 32 < NTOK) ? a[lane + 32] : -1e30f;
            float m = fmaxf(v0, v1);
            #pragma unroll
            for (int off = 16; off; off >>= 1)
                m = fmaxf(m, __shfl_xor_sync(0xffffffffu, m, off));
            float e0 = (lane < NTOK)      ? __expf(v0 - m) : 0.f;
            float e1 = (lane + 32 < NTOK) ? __expf(v1 - m) : 0.f;
            float ssum = e0 + e1;
            #pragma unroll
            for (int off = 16; off; off >>= 1)
                ssum += __shfl_xor_sync(0xffffffffu, ssum, off);
            const float inv = 1.0f / ssum;
            if (lane < NTOK)      a[lane]      = e0 * inv;
            if (lane + 32 < NTOK) a[lane + 32] = e1 * inv;
        }
    }
    __syncthreads();

    // ---- phase 4: attn @ v; thread = (row-pair, 4 adjacent c) ----
    for (int u = tid; u < 25 * 32; u += TPB) {
        const int ib = u >> 5;
        const int cg = u & 31;
        const int c4 = cg * 4;
        const int h  = cg >> 3;
        const int i0 = ib;
        const bool has1 = (ib < 24);
        const int i1 = has1 ? ib + 25 : ib;

        const float* a0r = &s_attn[(h * NTOK + i0) * 52];
        const float* a1r = &s_attn[(h * NTOK + i1) * 52];
        const float* vr  = &s_v[c4];

        u64 o0a = 0ull, o0b = 0ull, o1a = 0ull, o1b = 0ull;
        #pragma unroll 7
        for (int j = 0; j < NTOK; ++j) {
            const ulonglong2 vv = *reinterpret_cast<const ulonglong2*>(&vr[j * 128]);
            const float av0 = a0r[j];
            const float av1 = a1r[j];
            const u64 a0p = pack2(av0, av0);
            const u64 a1p = pack2(av1, av1);
            fma2(o0a, vv.x, a0p); fma2(o0b, vv.y, a0p);
            fma2(o1a, vv.x, a1p); fma2(o1b, vv.y, a1p);
        }
        const float2 f0a = unpack2(o0a), f0b = unpack2(o0b);
        float4 w0; w0.x = f0a.x; w0.y = f0a.y; w0.z = f0b.x; w0.w = f0b.y;
        *reinterpret_cast<float4*>(&s_o[i0 * 128 + c4]) = w0;
        if (has1) {
            const float2 f1a = unpack2(o1a), f1b = unpack2(o1b);
            float4 w1; w1.x = f1a.x; w1.y = f1a.y; w1.z = f1b.x; w1.w = f1b.y;
            *reinterpret_cast<float4*>(&s_o[i1 * 128 + c4]) = w1;
        }
    }
    __syncthreads();

    // ---- phase 5: output projection, f32x2 k-paired, register double-buffered ----
    {
        u64 acc[13];
        #pragma unroll
        for (int i = 0; i < 13; ++i) acc[i] = 0ull;

        const float* wp = proj_w + col;   // row stride 128

        float A0, A1, A2, A3, B0, B1, B2, B3;
        A0 = __ldg(&wp[0 * 128]); A1 = __ldg(&wp[1 * 128]);
        A2 = __ldg(&wp[2 * 128]); A3 = __ldg(&wp[3 * 128]);

        #pragma unroll 1
        for (int k8 = 0; k8 < 128; k8 += 8) {
            // prefetch B (k8+4..k8+7); always in range (last stage: 124..127)
            B0 = __ldg(&wp[(size_t)(k8 + 4) * 128]);
            B1 = __ldg(&wp[(size_t)(k8 + 5) * 128]);
            B2 = __ldg(&wp[(size_t)(k8 + 6) * 128]);
            B3 = __ldg(&wp[(size_t)(k8 + 7) * 128]);
            {
                const u64 w01 = pack2(A0, A1);
                const u64 w23 = pack2(A2, A3);
                #pragma unroll
                for (int i = 0; i < 13; ++i) {
                    const ulonglong2 ov = *reinterpret_cast<const ulonglong2*>(&s_o[(rbase + i) * 128 + k8]);
                    fma2(acc[i], ov.x, w01);
                    fma2(acc[i], ov.y, w23);
                }
            }
            // prefetch A (k8+8..k8+11), clamped on final iteration
            {
                const int kn = (k8 + 8 < 128) ? (k8 + 8) : 124;
                A0 = __ldg(&wp[(size_t)(kn + 0) * 128]);
                A1 = __ldg(&wp[(size_t)(kn + 1) * 128]);
                A2 = __ldg(&wp[(size_t)(kn + 2) * 128]);
                A3 = __ldg(&wp[(size_t)(kn + 3) * 128]);
            }
            {
                const u64 w01 = pack2(B0, B1);
                const u64 w23 = pack2(B2, B3);
                #pragma unroll
                for (int i = 0; i < 13; ++i) {
                    const ulonglong2 ov = *reinterpret_cast<const ulonglong2*>(&s_o[(rbase + i) * 128 + k8 + 4]);
                    fma2(acc[i], ov.x, w01);
                    fma2(acc[i], ov.y, w23);
                }
            }
        }
        const float bv = __ldg(&proj_b[col]);
        float* o = out + (size_t)blk * (NTOK * CDIM);
        for (int i = 0; i < rcnt; ++i) {
            const float2 f = unpack2(acc[i]);
            o[(rbase + i) * 128 + col] = f.x + f.y + bv;
        }
    }
}

extern "C" void kernel_launch(void* const* d_in, const int* in_sizes, int n_in,
                              void* d_out, int out_size)
{
    const float* x      = (const float*)d_in[0];
    const float* mask   = (const float*)d_in[1];
    const float* qkv_w  = (const float*)d_in[2];
    const float* qkv_b  = (const float*)d_in[3];
    const float* proj_w = (const float*)d_in[4];
    const float* proj_b = (const float*)d_in[5];
    const float* rel    = (const float*)d_in[6];
    float* out = (float*)d_out;

    cudaFuncSetAttribute(swin_window_attn_kernel,
                         cudaFuncAttributeMaxDynamicSharedMemorySize, SMEM_BYTES);
    swin_window_attn_kernel<<<2048, TPB, SMEM_BYTES>>>(
        x, mask, qkv_w, qkv_b, proj_w, proj_b, rel, out);
}